// round 1
// baseline (speedup 1.0000x reference)
#include <cuda_runtime.h>
#include <cstdint>

// Problem constants
#define BATCH   4
#define S_LEN   2048
#define DM      1024
#define NH      16
#define DK      64
#define M_TOT   (BATCH * S_LEN)   // 8192

// ---------------------------------------------------------------------------
// Scratch (device globals; no dynamic allocation allowed)
// ---------------------------------------------------------------------------
__device__ float g_Q[(size_t)BATCH * NH * S_LEN * DK];   // [bh, s, d]
__device__ float g_K[(size_t)BATCH * NH * S_LEN * DK];
__device__ float g_V[(size_t)BATCH * NH * S_LEN * DK];
__device__ float g_O[(size_t)M_TOT * DM];                // attn out, [b*s, e]
__device__ float g_Y[(size_t)M_TOT * DM];                // pre-LN residual sum

// ---------------------------------------------------------------------------
// Tiled fp32 GEMM: C[m][n] = sum_k A[m][k] * W[n][k]   (torch-style y = x W^T)
// BM=BN=64, BK=16, 256 threads, 4x4 micro-tile per thread.
// MODE 0: A = X (input x), scatter output into g_Q/g_K/g_V as [bh, s, d]
// MODE 1: A = g_O, output = acc + bias[n] + X[m][n] (residual) -> g_Y
// ---------------------------------------------------------------------------
template <int MODE>
__global__ void __launch_bounds__(256) gemm64(const float* __restrict__ X,
                                              const float* __restrict__ W,
                                              const float* __restrict__ bias,
                                              int which)
{
    __shared__ float As[16][64];   // [k][m]
    __shared__ float Bs[16][64];   // [k][n]

    const int tid = threadIdx.x;
    const int m0  = blockIdx.y * 64;
    const int n0  = blockIdx.x * 64;
    const int tm  = tid >> 4;          // 0..15
    const int tn  = tid & 15;          // 0..15
    const int lr  = tid >> 2;          // 0..63  (load row)
    const int lc  = (tid & 3) << 2;    // 0,4,8,12 (load col, float4)

    const float* A = (MODE == 0) ? X : g_O;

    float acc[4][4];
#pragma unroll
    for (int i = 0; i < 4; i++)
#pragma unroll
        for (int j = 0; j < 4; j++) acc[i][j] = 0.0f;

    for (int kt = 0; kt < DM; kt += 16) {
        float4 a4 = *(const float4*)(A + (size_t)(m0 + lr) * DM + kt + lc);
        float4 b4 = *(const float4*)(W + (size_t)(n0 + lr) * DM + kt + lc);
        __syncthreads();   // protect previous tile reads
        As[lc + 0][lr] = a4.x; As[lc + 1][lr] = a4.y;
        As[lc + 2][lr] = a4.z; As[lc + 3][lr] = a4.w;
        Bs[lc + 0][lr] = b4.x; Bs[lc + 1][lr] = b4.y;
        Bs[lc + 2][lr] = b4.z; Bs[lc + 3][lr] = b4.w;
        __syncthreads();

#pragma unroll
        for (int kk = 0; kk < 16; kk++) {
            float4 av = *(const float4*)(&As[kk][tm << 2]);
            float4 bv = *(const float4*)(&Bs[kk][tn << 2]);
            float a[4] = {av.x, av.y, av.z, av.w};
            float b[4] = {bv.x, bv.y, bv.z, bv.w};
#pragma unroll
            for (int i = 0; i < 4; i++)
#pragma unroll
                for (int j = 0; j < 4; j++) acc[i][j] += a[i] * b[j];
        }
    }

    if (MODE == 0) {
        float* C = (which == 0) ? g_Q : (which == 1) ? g_K : g_V;
#pragma unroll
        for (int i = 0; i < 4; i++) {
            const int m = m0 + (tm << 2) + i;
            const int b = m >> 11;          // / 2048
            const int s = m & (S_LEN - 1);
#pragma unroll
            for (int j = 0; j < 4; j++) {
                const int n = n0 + (tn << 2) + j;
                const int h = n >> 6;       // / 64
                const int d = n & 63;
                C[(((size_t)((b << 4) + h)) * S_LEN + s) * DK + d] = acc[i][j];
            }
        }
    } else {
#pragma unroll
        for (int i = 0; i < 4; i++) {
            const int m = m0 + (tm << 2) + i;
#pragma unroll
            for (int j = 0; j < 4; j++) {
                const int n = n0 + (tn << 2) + j;
                g_Y[(size_t)m * DM + n] = acc[i][j] + bias[n] + X[(size_t)m * DM + n];
            }
        }
    }
}

// ---------------------------------------------------------------------------
// Flash attention (fp32, online softmax). One thread owns one query row.
// Grid: (S_LEN/256, B*H). Block: 256 threads.
// Loops over key tiles of 64, processing scores in chunks of 16.
// ---------------------------------------------------------------------------
__global__ void __launch_bounds__(256) flash_attn()
{
    const int bh  = blockIdx.y;                       // 0..63
    const int row = blockIdx.x * 256 + threadIdx.x;   // query index in S
    const int tid = threadIdx.x;

    const float* Qb = g_Q + (size_t)bh * S_LEN * DK;
    const float* Kb = g_K + (size_t)bh * S_LEN * DK;
    const float* Vb = g_V + (size_t)bh * S_LEN * DK;

    __shared__ float Ks[64][64];
    __shared__ float Vs[64][64];

    // Load this thread's query row, pre-scaled by 1/sqrt(dk) = 0.125
    float q[DK];
#pragma unroll
    for (int k = 0; k < DK; k += 4) {
        float4 t = *(const float4*)(Qb + (size_t)row * DK + k);
        q[k + 0] = t.x * 0.125f; q[k + 1] = t.y * 0.125f;
        q[k + 2] = t.z * 0.125f; q[k + 3] = t.w * 0.125f;
    }

    float acc[DK];
#pragma unroll
    for (int d = 0; d < DK; d++) acc[d] = 0.0f;
    float mmax = -1e30f;
    float lsum = 0.0f;

    const int lr = tid >> 2;            // 0..63
    const int lc = (tid & 3) << 4;      // 0,16,32,48

    for (int kt = 0; kt < S_LEN; kt += 64) {
        __syncthreads();
#pragma unroll
        for (int i = 0; i < 16; i += 4) {
            *(float4*)&Ks[lr][lc + i] = *(const float4*)(Kb + (size_t)(kt + lr) * DK + lc + i);
            *(float4*)&Vs[lr][lc + i] = *(const float4*)(Vb + (size_t)(kt + lr) * DK + lc + i);
        }
        __syncthreads();

#pragma unroll
        for (int c = 0; c < 64; c += 16) {
            float s[16];
#pragma unroll
            for (int j = 0; j < 16; j++) {
                float sum = 0.0f;
#pragma unroll
                for (int k = 0; k < DK; k += 4) {
                    float4 kv = *(const float4*)&Ks[c + j][k];
                    sum += q[k] * kv.x + q[k + 1] * kv.y + q[k + 2] * kv.z + q[k + 3] * kv.w;
                }
                s[j] = sum;
            }
            float cm = s[0];
#pragma unroll
            for (int j = 1; j < 16; j++) cm = fmaxf(cm, s[j]);
            const float mnew  = fmaxf(mmax, cm);
            const float scale = __expf(mmax - mnew);
            float psum = 0.0f;
#pragma unroll
            for (int j = 0; j < 16; j++) { s[j] = __expf(s[j] - mnew); psum += s[j]; }
            lsum = lsum * scale + psum;
            mmax = mnew;
#pragma unroll
            for (int d = 0; d < DK; d++) acc[d] *= scale;
#pragma unroll
            for (int j = 0; j < 16; j++) {
                const float p = s[j];
#pragma unroll
                for (int d = 0; d < DK; d += 4) {
                    float4 vv = *(const float4*)&Vs[c + j][d];
                    acc[d + 0] += p * vv.x; acc[d + 1] += p * vv.y;
                    acc[d + 2] += p * vv.z; acc[d + 3] += p * vv.w;
                }
            }
        }
    }

    const float inv = 1.0f / lsum;
    const int b = bh >> 4;
    const int h = bh & 15;
    float* Op = g_O + ((size_t)(b * S_LEN + row)) * DM + h * DK;
#pragma unroll
    for (int d = 0; d < DK; d += 4) {
        float4 o;
        o.x = acc[d + 0] * inv; o.y = acc[d + 1] * inv;
        o.z = acc[d + 2] * inv; o.w = acc[d + 3] * inv;
        *(float4*)(Op + d) = o;
    }
}

// ---------------------------------------------------------------------------
// LayerNorm over last dim (1024). One block (256 threads) per row.
// ---------------------------------------------------------------------------
__global__ void __launch_bounds__(256) layernorm_k(const float* __restrict__ g,
                                                   const float* __restrict__ be,
                                                   float* __restrict__ out)
{
    const size_t rowbase = (size_t)blockIdx.x * DM;
    const int tid  = threadIdx.x;
    const int col  = tid << 2;

    float4 v = *(const float4*)(g_Y + rowbase + col);
    float sum = v.x + v.y + v.z + v.w;
    float sq  = v.x * v.x + v.y * v.y + v.z * v.z + v.w * v.w;

#pragma unroll
    for (int off = 16; off > 0; off >>= 1) {
        sum += __shfl_xor_sync(0xffffffffu, sum, off);
        sq  += __shfl_xor_sync(0xffffffffu, sq,  off);
    }
    __shared__ float s1[8], s2[8];
    const int warp = tid >> 5;
    if ((tid & 31) == 0) { s1[warp] = sum; s2[warp] = sq; }
    __syncthreads();
    float tot = 0.0f, totsq = 0.0f;
#pragma unroll
    for (int w = 0; w < 8; w++) { tot += s1[w]; totsq += s2[w]; }

    const float mean = tot * (1.0f / DM);
    const float var  = totsq * (1.0f / DM) - mean * mean;
    const float r    = rsqrtf(var + 1e-5f);

    float4 gg = *(const float4*)(g + col);
    float4 bb = *(const float4*)(be + col);
    float4 o;
    o.x = (v.x - mean) * r * gg.x + bb.x;
    o.y = (v.y - mean) * r * gg.y + bb.y;
    o.z = (v.z - mean) * r * gg.z + bb.z;
    o.w = (v.w - mean) * r * gg.w + bb.w;
    *(float4*)(out + rowbase + col) = o;
}

// ---------------------------------------------------------------------------
// Launcher
// ---------------------------------------------------------------------------
extern "C" void kernel_launch(void* const* d_in, const int* in_sizes, int n_in,
                              void* d_out, int out_size)
{
    const float* x    = (const float*)d_in[0];
    const float* w_q  = (const float*)d_in[1];
    const float* w_k  = (const float*)d_in[2];
    const float* w_v  = (const float*)d_in[3];
    const float* w_o  = (const float*)d_in[4];
    const float* b_o  = (const float*)d_in[5];
    const float* ln_g = (const float*)d_in[6];
    const float* ln_b = (const float*)d_in[7];
    float* out = (float*)d_out;

    dim3 gGemm(DM / 64, M_TOT / 64);   // (16, 128)
    dim3 bGemm(256);

    gemm64<0><<<gGemm, bGemm>>>(x, w_q, nullptr, 0);
    gemm64<0><<<gGemm, bGemm>>>(x, w_k, nullptr, 1);
    gemm64<0><<<gGemm, bGemm>>>(x, w_v, nullptr, 2);

    dim3 gAttn(S_LEN / 256, BATCH * NH);  // (8, 64)
    flash_attn<<<gAttn, 256>>>();

    gemm64<1><<<gGemm, bGemm>>>(x, w_o, b_o, 0);

    layernorm_k<<<M_TOT, 256>>>(ln_g, ln_b, out);
}

// round 3
// speedup vs baseline: 1.2536x; 1.2536x over previous
#include <cuda_runtime.h>
#include <cstdint>

#define BATCH   4
#define S_LEN   2048
#define DM      1024
#define NH      16
#define DK      64
#define M_TOT   (BATCH * S_LEN)   // 8192

// ---------------------------------------------------------------------------
// Scratch (device globals; no dynamic allocation allowed)
// ---------------------------------------------------------------------------
__device__ float g_Q[(size_t)BATCH * NH * S_LEN * DK];   // [bh, s, d]
__device__ float g_K[(size_t)BATCH * NH * S_LEN * DK];
__device__ float g_V[(size_t)BATCH * NH * S_LEN * DK];
__device__ float g_O[(size_t)M_TOT * DM];                // attn out, [b*s, e]
__device__ float g_Y[(size_t)M_TOT * DM];                // pre-LN residual sum

// ---------------------------------------------------------------------------
// mma.sync tf32 m16n8k8 (base-target PTX; runs on tensor pipe)
// ---------------------------------------------------------------------------
__device__ __forceinline__ void mma_tf32(float* c, const uint32_t* a, const uint32_t* b) {
    asm volatile(
        "mma.sync.aligned.m16n8k8.row.col.f32.tf32.tf32.f32 "
        "{%0,%1,%2,%3}, {%4,%5,%6,%7}, {%8,%9}, {%0,%1,%2,%3};"
        : "+f"(c[0]), "+f"(c[1]), "+f"(c[2]), "+f"(c[3])
        : "r"(a[0]), "r"(a[1]), "r"(a[2]), "r"(a[3]), "r"(b[0]), "r"(b[1]));
}

__device__ __forceinline__ void cp_async16(uint32_t smem_addr, const void* gmem) {
    asm volatile("cp.async.cg.shared.global [%0], [%1], 16;"
                 :: "r"(smem_addr), "l"(gmem));
}
__device__ __forceinline__ void cp_commit() {
    asm volatile("cp.async.commit_group;" ::: "memory");
}
template <int N>
__device__ __forceinline__ void cp_wait() {
    asm volatile("cp.async.wait_group %0;" :: "n"(N) : "memory");
}
__device__ __forceinline__ uint32_t smem_u32(const void* p) {
    uint32_t a;
    asm("{ .reg .u64 t; cvta.to.shared.u64 t, %1; cvt.u32.u64 %0, t; }"
        : "=r"(a) : "l"(p));
    return a;
}

// ---------------------------------------------------------------------------
// tf32 tensor-core GEMM: C[m][n] = sum_k A[m][k] * W[n][k]   (y = x W^T)
// CTA 128x128, BK=32, 8 warps (2m x 4n), warp tile 64x32 (4x4 m16n8k8 atoms).
// Double-buffered cp.async. smem row stride 36 floats (conflict-free frags).
// MODE 0: A = X, scatter to g_Q/g_K/g_V as [bh, s, d]
// MODE 1: A = g_O, out = acc + bias + X (residual) -> g_Y
// ---------------------------------------------------------------------------
#define SM_STRIDE 36
#define TILE_FLTS (128 * SM_STRIDE)            // 4608 floats per matrix buffer
#define GEMM_SMEM (4 * TILE_FLTS * 4)          // 73728 bytes

template <int MODE>
__global__ void __launch_bounds__(256) gemm_tc(const float* __restrict__ X,
                                               const float* __restrict__ W,
                                               const float* __restrict__ bias,
                                               int which)
{
    extern __shared__ float sm[];
    const int tid = threadIdx.x;
    const int wid = tid >> 5;
    const int lane = tid & 31;
    const int gid = lane >> 2;       // 0..7
    const int tig = lane & 3;        // 0..3
    const int wm  = wid >> 2;        // 0..1
    const int wn  = wid & 3;         // 0..3
    const int m0  = blockIdx.y * 128;
    const int n0  = blockIdx.x * 128;

    const float* Ag = (MODE == 0) ? X : g_O;

    // load mapping: 256 threads, 128 rows x 32 cols (per matrix)
    const int lrow = tid >> 1;             // 0..127
    const int lcol = (tid & 1) << 4;       // 0 or 16

    float c[4][4][4];
#pragma unroll
    for (int mi = 0; mi < 4; mi++)
#pragma unroll
        for (int ni = 0; ni < 4; ni++)
#pragma unroll
            for (int r = 0; r < 4; r++) c[mi][ni][r] = 0.0f;

    const uint32_t smA[2] = { smem_u32(sm),                 smem_u32(sm + 2 * TILE_FLTS) };
    const uint32_t smB[2] = { smem_u32(sm + TILE_FLTS),     smem_u32(sm + 3 * TILE_FLTS) };

    auto load_tile = [&](int kt, int buf) {
        const int kbase = kt << 5;
        const float* agp = Ag + (size_t)(m0 + lrow) * DM + kbase + lcol;
        const float* wgp = W  + (size_t)(n0 + lrow) * DM + kbase + lcol;
        const uint32_t sa = smA[buf] + (lrow * SM_STRIDE + lcol) * 4;
        const uint32_t sb = smB[buf] + (lrow * SM_STRIDE + lcol) * 4;
#pragma unroll
        for (int i = 0; i < 4; i++) {
            cp_async16(sa + i * 16, agp + i * 4);
            cp_async16(sb + i * 16, wgp + i * 4);
        }
    };

    load_tile(0, 0);
    cp_commit();

    for (int kt = 0; kt < 32; ++kt) {
        if (kt + 1 < 32) {
            load_tile(kt + 1, (kt + 1) & 1);
            cp_commit();
            cp_wait<1>();
        } else {
            cp_wait<0>();
        }
        __syncthreads();

        const float* As = sm + ((kt & 1) ? 2 * TILE_FLTS : 0);
        const float* Bs = sm + ((kt & 1) ? 3 * TILE_FLTS : TILE_FLTS);
        const float* Aw = As + (wm * 64 + gid) * SM_STRIDE;
        const float* Bw = Bs + (wn * 32 + gid) * SM_STRIDE;

#pragma unroll
        for (int ka = 0; ka < 4; ka++) {
            const int kc = ka << 3;
            uint32_t af[4][4], bf[4][2];
#pragma unroll
            for (int mi = 0; mi < 4; mi++) {
                const float* p = Aw + mi * 16 * SM_STRIDE + kc;
                af[mi][0] = __float_as_uint(p[tig]);
                af[mi][1] = __float_as_uint(p[8 * SM_STRIDE + tig]);
                af[mi][2] = __float_as_uint(p[tig + 4]);
                af[mi][3] = __float_as_uint(p[8 * SM_STRIDE + tig + 4]);
            }
#pragma unroll
            for (int ni = 0; ni < 4; ni++) {
                const float* p = Bw + ni * 8 * SM_STRIDE + kc;
                bf[ni][0] = __float_as_uint(p[tig]);
                bf[ni][1] = __float_as_uint(p[tig + 4]);
            }
#pragma unroll
            for (int mi = 0; mi < 4; mi++)
#pragma unroll
                for (int ni = 0; ni < 4; ni++)
                    mma_tf32(c[mi][ni], af[mi], bf[ni]);
        }
        __syncthreads();
    }

    // Epilogue. c0,c1: row = base+gid, cols tig*2, tig*2+1; c2,c3: row+8.
#pragma unroll
    for (int mi = 0; mi < 4; mi++) {
#pragma unroll
        for (int half = 0; half < 2; half++) {
            const int m = m0 + wm * 64 + mi * 16 + gid + half * 8;
#pragma unroll
            for (int ni = 0; ni < 4; ni++) {
                const int n = n0 + wn * 32 + ni * 8 + tig * 2;
                float2 v;
                v.x = c[mi][ni][half * 2 + 0];
                v.y = c[mi][ni][half * 2 + 1];
                if (MODE == 0) {
                    float* C = (which == 0) ? g_Q : (which == 1) ? g_K : g_V;
                    const int b = m >> 11;
                    const int s = m & (S_LEN - 1);
                    const int h = n >> 6;
                    const int d = n & 63;
                    *(float2*)(C + (((size_t)(b * NH + h)) * S_LEN + s) * DK + d) = v;
                } else {
                    const float* xp = X + (size_t)m * DM + n;
                    v.x += bias[n]     + xp[0];
                    v.y += bias[n + 1] + xp[1];
                    *(float2*)(g_Y + (size_t)m * DM + n) = v;
                }
            }
        }
    }
}

// ---------------------------------------------------------------------------
// Flash attention (fp32, online softmax). One thread owns one query row.
// ---------------------------------------------------------------------------
__global__ void __launch_bounds__(256) flash_attn()
{
    const int bh  = blockIdx.y;
    const int row = blockIdx.x * 256 + threadIdx.x;
    const int tid = threadIdx.x;

    const float* Qb = g_Q + (size_t)bh * S_LEN * DK;
    const float* Kb = g_K + (size_t)bh * S_LEN * DK;
    const float* Vb = g_V + (size_t)bh * S_LEN * DK;

    __shared__ float Ks[64][64];
    __shared__ float Vs[64][64];

    float q[DK];
#pragma unroll
    for (int k = 0; k < DK; k += 4) {
        float4 t = *(const float4*)(Qb + (size_t)row * DK + k);
        q[k + 0] = t.x * 0.125f; q[k + 1] = t.y * 0.125f;
        q[k + 2] = t.z * 0.125f; q[k + 3] = t.w * 0.125f;
    }

    float acc[DK];
#pragma unroll
    for (int d = 0; d < DK; d++) acc[d] = 0.0f;
    float mmax = -1e30f;
    float lsum = 0.0f;

    const int lr = tid >> 2;
    const int lc = (tid & 3) << 4;

    for (int kt = 0; kt < S_LEN; kt += 64) {
        __syncthreads();
#pragma unroll
        for (int i = 0; i < 16; i += 4) {
            *(float4*)&Ks[lr][lc + i] = *(const float4*)(Kb + (size_t)(kt + lr) * DK + lc + i);
            *(float4*)&Vs[lr][lc + i] = *(const float4*)(Vb + (size_t)(kt + lr) * DK + lc + i);
        }
        __syncthreads();

#pragma unroll
        for (int c = 0; c < 64; c += 16) {
            float s[16];
#pragma unroll
            for (int j = 0; j < 16; j++) {
                float sum = 0.0f;
#pragma unroll
                for (int k = 0; k < DK; k += 4) {
                    float4 kv = *(const float4*)&Ks[c + j][k];
                    sum += q[k] * kv.x + q[k + 1] * kv.y + q[k + 2] * kv.z + q[k + 3] * kv.w;
                }
                s[j] = sum;
            }
            float cm = s[0];
#pragma unroll
            for (int j = 1; j < 16; j++) cm = fmaxf(cm, s[j]);
            const float mnew  = fmaxf(mmax, cm);
            const float scale = __expf(mmax - mnew);
            float psum = 0.0f;
#pragma unroll
            for (int j = 0; j < 16; j++) { s[j] = __expf(s[j] - mnew); psum += s[j]; }
            lsum = lsum * scale + psum;
            mmax = mnew;
#pragma unroll
            for (int d = 0; d < DK; d++) acc[d] *= scale;
#pragma unroll
            for (int j = 0; j < 16; j++) {
                const float p = s[j];
#pragma unroll
                for (int d = 0; d < DK; d += 4) {
                    float4 vv = *(const float4*)&Vs[c + j][d];
                    acc[d + 0] += p * vv.x; acc[d + 1] += p * vv.y;
                    acc[d + 2] += p * vv.z; acc[d + 3] += p * vv.w;
                }
            }
        }
    }

    const float inv = 1.0f / lsum;
    const int b = bh >> 4;
    const int h = bh & 15;
    float* Op = g_O + ((size_t)(b * S_LEN + row)) * DM + h * DK;
#pragma unroll
    for (int d = 0; d < DK; d += 4) {
        float4 o;
        o.x = acc[d + 0] * inv; o.y = acc[d + 1] * inv;
        o.z = acc[d + 2] * inv; o.w = acc[d + 3] * inv;
        *(float4*)(Op + d) = o;
    }
}

// ---------------------------------------------------------------------------
// LayerNorm over last dim (1024). One block (256 threads) per row.
// ---------------------------------------------------------------------------
__global__ void __launch_bounds__(256) layernorm_k(const float* __restrict__ g,
                                                   const float* __restrict__ be,
                                                   float* __restrict__ out)
{
    const size_t rowbase = (size_t)blockIdx.x * DM;
    const int tid = threadIdx.x;
    const int col = tid << 2;

    float4 v = *(const float4*)(g_Y + rowbase + col);
    float sum = v.x + v.y + v.z + v.w;
    float sq  = v.x * v.x + v.y * v.y + v.z * v.z + v.w * v.w;

#pragma unroll
    for (int off = 16; off > 0; off >>= 1) {
        sum += __shfl_xor_sync(0xffffffffu, sum, off);
        sq  += __shfl_xor_sync(0xffffffffu, sq,  off);
    }
    __shared__ float s1[8], s2[8];
    const int warp = tid >> 5;
    if ((tid & 31) == 0) { s1[warp] = sum; s2[warp] = sq; }
    __syncthreads();
    float tot = 0.0f, totsq = 0.0f;
#pragma unroll
    for (int w = 0; w < 8; w++) { tot += s1[w]; totsq += s2[w]; }

    const float mean = tot * (1.0f / DM);
    const float var  = totsq * (1.0f / DM) - mean * mean;
    const float r    = rsqrtf(var + 1e-5f);

    float4 gg = *(const float4*)(g + col);
    float4 bb = *(const float4*)(be + col);
    float4 o;
    o.x = (v.x - mean) * r * gg.x + bb.x;
    o.y = (v.y - mean) * r * gg.y + bb.y;
    o.z = (v.z - mean) * r * gg.z + bb.z;
    o.w = (v.w - mean) * r * gg.w + bb.w;
    *(float4*)(out + rowbase + col) = o;
}

// ---------------------------------------------------------------------------
// Launcher
// ---------------------------------------------------------------------------
extern "C" void kernel_launch(void* const* d_in, const int* in_sizes, int n_in,
                              void* d_out, int out_size)
{
    const float* x    = (const float*)d_in[0];
    const float* w_q  = (const float*)d_in[1];
    const float* w_k  = (const float*)d_in[2];
    const float* w_v  = (const float*)d_in[3];
    const float* w_o  = (const float*)d_in[4];
    const float* b_o  = (const float*)d_in[5];
    const float* ln_g = (const float*)d_in[6];
    const float* ln_b = (const float*)d_in[7];
    float* out = (float*)d_out;

    cudaFuncSetAttribute(gemm_tc<0>, cudaFuncAttributeMaxDynamicSharedMemorySize, GEMM_SMEM);
    cudaFuncSetAttribute(gemm_tc<1>, cudaFuncAttributeMaxDynamicSharedMemorySize, GEMM_SMEM);

    dim3 gGemm(DM / 128, M_TOT / 128);   // (8, 64)

    gemm_tc<0><<<gGemm, 256, GEMM_SMEM>>>(x, w_q, nullptr, 0);
    gemm_tc<0><<<gGemm, 256, GEMM_SMEM>>>(x, w_k, nullptr, 1);
    gemm_tc<0><<<gGemm, 256, GEMM_SMEM>>>(x, w_v, nullptr, 2);

    dim3 gAttn(S_LEN / 256, BATCH * NH);  // (8, 64)
    flash_attn<<<gAttn, 256>>>();

    gemm_tc<1><<<gGemm, 256, GEMM_SMEM>>>(x, w_o, b_o, 0);

    layernorm_k<<<M_TOT, 256>>>(ln_g, ln_b, out);
}

// round 4
// speedup vs baseline: 3.8682x; 3.0855x over previous
#include <cuda_runtime.h>
#include <cstdint>

#define BATCH   4
#define S_LEN   2048
#define DM      1024
#define NH      16
#define DK      64
#define M_TOT   (BATCH * S_LEN)   // 8192

// ---------------------------------------------------------------------------
// Scratch (device globals; no dynamic allocation allowed)
// ---------------------------------------------------------------------------
__device__ float g_Q[(size_t)BATCH * NH * S_LEN * DK];   // [bh, s, d]
__device__ float g_K[(size_t)BATCH * NH * S_LEN * DK];
__device__ float g_V[(size_t)BATCH * NH * S_LEN * DK];
__device__ float g_O[(size_t)M_TOT * DM];                // attn out, [b*s, e]
__device__ float g_Y[(size_t)M_TOT * DM];                // pre-LN residual sum

// ---------------------------------------------------------------------------
// mma.sync tf32 m16n8k8 (base-target PTX; runs on tensor pipe)
// ---------------------------------------------------------------------------
__device__ __forceinline__ void mma_tf32(float* c, const uint32_t* a, const uint32_t* b) {
    asm volatile(
        "mma.sync.aligned.m16n8k8.row.col.f32.tf32.tf32.f32 "
        "{%0,%1,%2,%3}, {%4,%5,%6,%7}, {%8,%9}, {%0,%1,%2,%3};"
        : "+f"(c[0]), "+f"(c[1]), "+f"(c[2]), "+f"(c[3])
        : "r"(a[0]), "r"(a[1]), "r"(a[2]), "r"(a[3]), "r"(b[0]), "r"(b[1]));
}

__device__ __forceinline__ void cp_async16(uint32_t smem_addr, const void* gmem) {
    asm volatile("cp.async.cg.shared.global [%0], [%1], 16;"
                 :: "r"(smem_addr), "l"(gmem));
}
__device__ __forceinline__ void cp_commit() {
    asm volatile("cp.async.commit_group;" ::: "memory");
}
template <int N>
__device__ __forceinline__ void cp_wait() {
    asm volatile("cp.async.wait_group %0;" :: "n"(N) : "memory");
}
__device__ __forceinline__ uint32_t smem_u32(const void* p) {
    uint32_t a;
    asm("{ .reg .u64 t; cvta.to.shared.u64 t, %1; cvt.u32.u64 %0, t; }"
        : "=r"(a) : "l"(p));
    return a;
}

// ---------------------------------------------------------------------------
// tf32 tensor-core GEMM: C[m][n] = sum_k A[m][k] * W[n][k]   (y = x W^T)
// CTA 128x128, BK=32, 8 warps (2m x 4n), warp tile 64x32 (4x4 m16n8k8 atoms).
// MODE 0: A = X, W selected by blockIdx.z, scatter to g_Q/g_K/g_V as [bh,s,d]
// MODE 1: A = g_O, out = acc + bias + X (residual) -> g_Y
// ---------------------------------------------------------------------------
#define SM_STRIDE 36
#define TILE_FLTS (128 * SM_STRIDE)            // 4608 floats per matrix buffer
#define GEMM_SMEM (4 * TILE_FLTS * 4)          // 73728 bytes

template <int MODE>
__global__ void __launch_bounds__(256) gemm_tc(const float* __restrict__ X,
                                               const float* __restrict__ W0,
                                               const float* __restrict__ W1,
                                               const float* __restrict__ W2,
                                               const float* __restrict__ bias)
{
    extern __shared__ float sm[];
    const int tid = threadIdx.x;
    const int wid = tid >> 5;
    const int lane = tid & 31;
    const int gid = lane >> 2;       // 0..7
    const int tig = lane & 3;        // 0..3
    const int wm  = wid >> 2;        // 0..1
    const int wn  = wid & 3;         // 0..3
    const int m0  = blockIdx.y * 128;
    const int n0  = blockIdx.x * 128;
    const int which = blockIdx.z;

    const float* Ag = (MODE == 0) ? X : g_O;
    const float* W  = (which == 0) ? W0 : (which == 1) ? W1 : W2;

    const int lrow = tid >> 1;             // 0..127
    const int lcol = (tid & 1) << 4;       // 0 or 16

    float c[4][4][4];
#pragma unroll
    for (int mi = 0; mi < 4; mi++)
#pragma unroll
        for (int ni = 0; ni < 4; ni++)
#pragma unroll
            for (int r = 0; r < 4; r++) c[mi][ni][r] = 0.0f;

    const uint32_t smA[2] = { smem_u32(sm),                 smem_u32(sm + 2 * TILE_FLTS) };
    const uint32_t smB[2] = { smem_u32(sm + TILE_FLTS),     smem_u32(sm + 3 * TILE_FLTS) };

    auto load_tile = [&](int kt, int buf) {
        const int kbase = kt << 5;
        const float* agp = Ag + (size_t)(m0 + lrow) * DM + kbase + lcol;
        const float* wgp = W  + (size_t)(n0 + lrow) * DM + kbase + lcol;
        const uint32_t sa = smA[buf] + (lrow * SM_STRIDE + lcol) * 4;
        const uint32_t sb = smB[buf] + (lrow * SM_STRIDE + lcol) * 4;
#pragma unroll
        for (int i = 0; i < 4; i++) {
            cp_async16(sa + i * 16, agp + i * 4);
            cp_async16(sb + i * 16, wgp + i * 4);
        }
    };

    load_tile(0, 0);
    cp_commit();

    for (int kt = 0; kt < 32; ++kt) {
        if (kt + 1 < 32) {
            load_tile(kt + 1, (kt + 1) & 1);
            cp_commit();
            cp_wait<1>();
        } else {
            cp_wait<0>();
        }
        __syncthreads();

        const float* As = sm + ((kt & 1) ? 2 * TILE_FLTS : 0);
        const float* Bs = sm + ((kt & 1) ? 3 * TILE_FLTS : TILE_FLTS);
        const float* Aw = As + (wm * 64 + gid) * SM_STRIDE;
        const float* Bw = Bs + (wn * 32 + gid) * SM_STRIDE;

#pragma unroll
        for (int ka = 0; ka < 4; ka++) {
            const int kc = ka << 3;
            uint32_t af[4][4], bf[4][2];
#pragma unroll
            for (int mi = 0; mi < 4; mi++) {
                const float* p = Aw + mi * 16 * SM_STRIDE + kc;
                af[mi][0] = __float_as_uint(p[tig]);
                af[mi][1] = __float_as_uint(p[8 * SM_STRIDE + tig]);
                af[mi][2] = __float_as_uint(p[tig + 4]);
                af[mi][3] = __float_as_uint(p[8 * SM_STRIDE + tig + 4]);
            }
#pragma unroll
            for (int ni = 0; ni < 4; ni++) {
                const float* p = Bw + ni * 8 * SM_STRIDE + kc;
                bf[ni][0] = __float_as_uint(p[tig]);
                bf[ni][1] = __float_as_uint(p[tig + 4]);
            }
#pragma unroll
            for (int mi = 0; mi < 4; mi++)
#pragma unroll
                for (int ni = 0; ni < 4; ni++)
                    mma_tf32(c[mi][ni], af[mi], bf[ni]);
        }
        __syncthreads();
    }

#pragma unroll
    for (int mi = 0; mi < 4; mi++) {
#pragma unroll
        for (int half = 0; half < 2; half++) {
            const int m = m0 + wm * 64 + mi * 16 + gid + half * 8;
#pragma unroll
            for (int ni = 0; ni < 4; ni++) {
                const int n = n0 + wn * 32 + ni * 8 + tig * 2;
                float2 v;
                v.x = c[mi][ni][half * 2 + 0];
                v.y = c[mi][ni][half * 2 + 1];
                if (MODE == 0) {
                    float* C = (which == 0) ? g_Q : (which == 1) ? g_K : g_V;
                    const int b = m >> 11;
                    const int s = m & (S_LEN - 1);
                    const int h = n >> 6;
                    const int d = n & 63;
                    *(float2*)(C + (((size_t)(b * NH + h)) * S_LEN + s) * DK + d) = v;
                } else {
                    const float* xp = X + (size_t)m * DM + n;
                    v.x += bias[n]     + xp[0];
                    v.y += bias[n + 1] + xp[1];
                    *(float2*)(g_Y + (size_t)m * DM + n) = v;
                }
            }
        }
    }
}

// ---------------------------------------------------------------------------
// Tensor-core flash attention (tf32 mma, online softmax).
// Block: 128 threads (4 warps). CTA: 64 q-rows x full key loop. Warp: 16 q.
// smem: Qs[64][68], Ks[64][68], Vt[64][68] (V transposed), Ps[4][16][68].
// ---------------------------------------------------------------------------
#define AST 68
#define ATT_SMEM ((3 * 64 * AST + 4 * 16 * AST) * 4)   // 69632 B

__global__ void __launch_bounds__(128) flash_attn_tc()
{
    extern __shared__ float sm[];
    float* Qs = sm;                    // [64][AST]
    float* Ks = sm + 64 * AST;
    float* Vt = sm + 2 * 64 * AST;
    float* Ps = sm + 3 * 64 * AST;     // per warp [16][AST]

    const int tid  = threadIdx.x;
    const int wid  = tid >> 5;
    const int lane = tid & 31;
    const int gid  = lane >> 2;
    const int tig  = lane & 3;
    const int bh   = blockIdx.y;
    const int q0   = blockIdx.x * 64;

    const float* Qg = g_Q + (size_t)bh * S_LEN * DK;
    const float* Kg = g_K + (size_t)bh * S_LEN * DK;
    const float* Vg = g_V + (size_t)bh * S_LEN * DK;

    const int lrow = tid >> 1;            // 0..63
    const int lcol = (tid & 1) << 5;      // 0 or 32

    // Load Q tile, pre-scaled by 1/sqrt(dk)
#pragma unroll
    for (int i = 0; i < 8; i++) {
        float4 v = *(const float4*)(Qg + (size_t)(q0 + lrow) * DK + lcol + i * 4);
        v.x *= 0.125f; v.y *= 0.125f; v.z *= 0.125f; v.w *= 0.125f;
        *(float4*)(Qs + lrow * AST + lcol + i * 4) = v;
    }
    __syncthreads();

    // Persistent Q fragments (warp rows wid*16 + gid, +8)
    uint32_t aq[8][4];
    {
        const float* Qw = Qs + (wid * 16 + gid) * AST;
#pragma unroll
        for (int ka = 0; ka < 8; ka++) {
            const int kc = ka << 3;
            aq[ka][0] = __float_as_uint(Qw[kc + tig]);
            aq[ka][1] = __float_as_uint(Qw[8 * AST + kc + tig]);
            aq[ka][2] = __float_as_uint(Qw[kc + tig + 4]);
            aq[ka][3] = __float_as_uint(Qw[8 * AST + kc + tig + 4]);
        }
    }

    float co[8][4];
#pragma unroll
    for (int ni = 0; ni < 8; ni++)
#pragma unroll
        for (int r = 0; r < 4; r++) co[ni][r] = 0.0f;
    float m0 = -1e30f, m1 = -1e30f, l0 = 0.0f, l1 = 0.0f;
    float* Pw = Ps + wid * 16 * AST;

    for (int kt = 0; kt < S_LEN; kt += 64) {
        __syncthreads();   // previous tile fully consumed
        // K tile -> Ks[key][d]; V tile -> Vt[d][key] (transposed)
#pragma unroll
        for (int i = 0; i < 8; i++) {
            *(float4*)(Ks + lrow * AST + lcol + i * 4) =
                *(const float4*)(Kg + (size_t)(kt + lrow) * DK + lcol + i * 4);
        }
#pragma unroll
        for (int i = 0; i < 8; i++) {
            float4 v = *(const float4*)(Vg + (size_t)(kt + lrow) * DK + lcol + i * 4);
            const int d = lcol + i * 4;
            Vt[(d + 0) * AST + lrow] = v.x;
            Vt[(d + 1) * AST + lrow] = v.y;
            Vt[(d + 2) * AST + lrow] = v.z;
            Vt[(d + 3) * AST + lrow] = v.w;
        }
        __syncthreads();

        // ---- scores: 16q x 64k via mma ----
        float cs[8][4];
#pragma unroll
        for (int ni = 0; ni < 8; ni++)
#pragma unroll
            for (int r = 0; r < 4; r++) cs[ni][r] = 0.0f;

#pragma unroll
        for (int ka = 0; ka < 8; ka++) {
            const int kc = ka << 3;
            uint32_t bf[8][2];
#pragma unroll
            for (int ni = 0; ni < 8; ni++) {
                const float* p = Ks + (ni * 8 + gid) * AST + kc;
                bf[ni][0] = __float_as_uint(p[tig]);
                bf[ni][1] = __float_as_uint(p[tig + 4]);
            }
#pragma unroll
            for (int ni = 0; ni < 8; ni++)
                mma_tf32(cs[ni], aq[ka], bf[ni]);
        }

        // ---- online softmax (rows gid and gid+8) ----
        float mt0 = -1e30f, mt1 = -1e30f;
#pragma unroll
        for (int ni = 0; ni < 8; ni++) {
            mt0 = fmaxf(mt0, fmaxf(cs[ni][0], cs[ni][1]));
            mt1 = fmaxf(mt1, fmaxf(cs[ni][2], cs[ni][3]));
        }
        mt0 = fmaxf(mt0, __shfl_xor_sync(0xffffffffu, mt0, 1));
        mt0 = fmaxf(mt0, __shfl_xor_sync(0xffffffffu, mt0, 2));
        mt1 = fmaxf(mt1, __shfl_xor_sync(0xffffffffu, mt1, 1));
        mt1 = fmaxf(mt1, __shfl_xor_sync(0xffffffffu, mt1, 2));

        const float m0n = fmaxf(m0, mt0);
        const float m1n = fmaxf(m1, mt1);
        const float sc0 = __expf(m0 - m0n);
        const float sc1 = __expf(m1 - m1n);
        float s0 = 0.0f, s1 = 0.0f;
#pragma unroll
        for (int ni = 0; ni < 8; ni++) {
            cs[ni][0] = __expf(cs[ni][0] - m0n);
            cs[ni][1] = __expf(cs[ni][1] - m0n);
            cs[ni][2] = __expf(cs[ni][2] - m1n);
            cs[ni][3] = __expf(cs[ni][3] - m1n);
            s0 += cs[ni][0] + cs[ni][1];
            s1 += cs[ni][2] + cs[ni][3];
        }
        s0 += __shfl_xor_sync(0xffffffffu, s0, 1);
        s0 += __shfl_xor_sync(0xffffffffu, s0, 2);
        s1 += __shfl_xor_sync(0xffffffffu, s1, 1);
        s1 += __shfl_xor_sync(0xffffffffu, s1, 2);
        l0 = l0 * sc0 + s0;
        l1 = l1 * sc1 + s1;
        m0 = m0n; m1 = m1n;
#pragma unroll
        for (int ni = 0; ni < 8; ni++) {
            co[ni][0] *= sc0; co[ni][1] *= sc0;
            co[ni][2] *= sc1; co[ni][3] *= sc1;
        }

        // ---- write P to warp-private smem ----
#pragma unroll
        for (int ni = 0; ni < 8; ni++) {
            float2 p0 = make_float2(cs[ni][0], cs[ni][1]);
            float2 p1 = make_float2(cs[ni][2], cs[ni][3]);
            *(float2*)(Pw + gid * AST + ni * 8 + 2 * tig)       = p0;
            *(float2*)(Pw + (gid + 8) * AST + ni * 8 + 2 * tig) = p1;
        }
        __syncwarp();

        // ---- out += P @ V ----
#pragma unroll
        for (int ka = 0; ka < 8; ka++) {
            const int kc = ka << 3;
            uint32_t ap[4];
            ap[0] = __float_as_uint(Pw[gid * AST + kc + tig]);
            ap[1] = __float_as_uint(Pw[(gid + 8) * AST + kc + tig]);
            ap[2] = __float_as_uint(Pw[gid * AST + kc + tig + 4]);
            ap[3] = __float_as_uint(Pw[(gid + 8) * AST + kc + tig + 4]);
#pragma unroll
            for (int ni = 0; ni < 8; ni++) {
                uint32_t bf[2];
                const float* p = Vt + (ni * 8 + gid) * AST + kc;
                bf[0] = __float_as_uint(p[tig]);
                bf[1] = __float_as_uint(p[tig + 4]);
                mma_tf32(co[ni], ap, bf);
            }
        }
    }

    // ---- epilogue: normalize and scatter into g_O [b*s][h*64+d] ----
    const float inv0 = 1.0f / l0;
    const float inv1 = 1.0f / l1;
    const int b = bh >> 4;
    const int h = bh & 15;
    const int r0 = q0 + wid * 16 + gid;
    float* O0 = g_O + (size_t)(b * S_LEN + r0) * DM + h * DK;
    float* O1 = g_O + (size_t)(b * S_LEN + r0 + 8) * DM + h * DK;
#pragma unroll
    for (int ni = 0; ni < 8; ni++) {
        float2 v0 = make_float2(co[ni][0] * inv0, co[ni][1] * inv0);
        float2 v1 = make_float2(co[ni][2] * inv1, co[ni][3] * inv1);
        *(float2*)(O0 + ni * 8 + 2 * tig) = v0;
        *(float2*)(O1 + ni * 8 + 2 * tig) = v1;
    }
}

// ---------------------------------------------------------------------------
// LayerNorm over last dim (1024). One block (256 threads) per row.
// ---------------------------------------------------------------------------
__global__ void __launch_bounds__(256) layernorm_k(const float* __restrict__ g,
                                                   const float* __restrict__ be,
                                                   float* __restrict__ out)
{
    const size_t rowbase = (size_t)blockIdx.x * DM;
    const int tid = threadIdx.x;
    const int col = tid << 2;

    float4 v = *(const float4*)(g_Y + rowbase + col);
    float sum = v.x + v.y + v.z + v.w;
    float sq  = v.x * v.x + v.y * v.y + v.z * v.z + v.w * v.w;

#pragma unroll
    for (int off = 16; off > 0; off >>= 1) {
        sum += __shfl_xor_sync(0xffffffffu, sum, off);
        sq  += __shfl_xor_sync(0xffffffffu, sq,  off);
    }
    __shared__ float s1[8], s2[8];
    const int warp = tid >> 5;
    if ((tid & 31) == 0) { s1[warp] = sum; s2[warp] = sq; }
    __syncthreads();
    float tot = 0.0f, totsq = 0.0f;
#pragma unroll
    for (int w = 0; w < 8; w++) { tot += s1[w]; totsq += s2[w]; }

    const float mean = tot * (1.0f / DM);
    const float var  = totsq * (1.0f / DM) - mean * mean;
    const float r    = rsqrtf(var + 1e-5f);

    float4 gg = *(const float4*)(g + col);
    float4 bb = *(const float4*)(be + col);
    float4 o;
    o.x = (v.x - mean) * r * gg.x + bb.x;
    o.y = (v.y - mean) * r * gg.y + bb.y;
    o.z = (v.z - mean) * r * gg.z + bb.z;
    o.w = (v.w - mean) * r * gg.w + bb.w;
    *(float4*)(out + rowbase + col) = o;
}

// ---------------------------------------------------------------------------
// Launcher
// ---------------------------------------------------------------------------
extern "C" void kernel_launch(void* const* d_in, const int* in_sizes, int n_in,
                              void* d_out, int out_size)
{
    const float* x    = (const float*)d_in[0];
    const float* w_q  = (const float*)d_in[1];
    const float* w_k  = (const float*)d_in[2];
    const float* w_v  = (const float*)d_in[3];
    const float* w_o  = (const float*)d_in[4];
    const float* b_o  = (const float*)d_in[5];
    const float* ln_g = (const float*)d_in[6];
    const float* ln_b = (const float*)d_in[7];
    float* out = (float*)d_out;

    cudaFuncSetAttribute(gemm_tc<0>, cudaFuncAttributeMaxDynamicSharedMemorySize, GEMM_SMEM);
    cudaFuncSetAttribute(gemm_tc<1>, cudaFuncAttributeMaxDynamicSharedMemorySize, GEMM_SMEM);
    cudaFuncSetAttribute(flash_attn_tc, cudaFuncAttributeMaxDynamicSharedMemorySize, ATT_SMEM);

    // Fused Q/K/V projections: one launch, z selects the weight matrix.
    dim3 gQKV(DM / 128, M_TOT / 128, 3);   // (8, 64, 3)
    gemm_tc<0><<<gQKV, 256, GEMM_SMEM>>>(x, w_q, w_k, w_v, nullptr);

    dim3 gAttn(S_LEN / 64, BATCH * NH);    // (32, 64)
    flash_attn_tc<<<gAttn, 128, ATT_SMEM>>>();

    dim3 gO(DM / 128, M_TOT / 128, 1);
    gemm_tc<1><<<gO, 256, GEMM_SMEM>>>(x, w_o, nullptr, nullptr, b_o);

    layernorm_k<<<M_TOT, 256>>>(ln_g, ln_b, out);
}

// round 5
// speedup vs baseline: 10.2683x; 2.6546x over previous
#include <cuda_runtime.h>
#include <cuda_fp16.h>
#include <cstdint>

#define BATCH   4
#define S_LEN   2048
#define DM      1024
#define NH      16
#define DK      64
#define M_TOT   (BATCH * S_LEN)   // 8192

// ---------------------------------------------------------------------------
// Scratch (device globals; no dynamic allocation allowed)
// ---------------------------------------------------------------------------
__device__ __half g_Xh[(size_t)M_TOT * DM];
__device__ __half g_Wq[(size_t)DM * DM];
__device__ __half g_Wk[(size_t)DM * DM];
__device__ __half g_Wv[(size_t)DM * DM];
__device__ __half g_Wo[(size_t)DM * DM];
__device__ __half g_Q[(size_t)BATCH * NH * S_LEN * DK];   // [bh, s, d] (pre-scaled)
__device__ __half g_K[(size_t)BATCH * NH * S_LEN * DK];
__device__ __half g_V[(size_t)BATCH * NH * S_LEN * DK];
__device__ __half g_O[(size_t)M_TOT * DM];                // attn out
__device__ float  g_Y[(size_t)M_TOT * DM];                // pre-LN residual sum

// ---------------------------------------------------------------------------
// PTX helpers (all base-target: sm_80+)
// ---------------------------------------------------------------------------
__device__ __forceinline__ void mma_f16(float* c, const uint32_t* a, const uint32_t* b) {
    asm volatile(
        "mma.sync.aligned.m16n8k16.row.col.f32.f16.f16.f32 "
        "{%0,%1,%2,%3}, {%4,%5,%6,%7}, {%8,%9}, {%0,%1,%2,%3};"
        : "+f"(c[0]), "+f"(c[1]), "+f"(c[2]), "+f"(c[3])
        : "r"(a[0]), "r"(a[1]), "r"(a[2]), "r"(a[3]), "r"(b[0]), "r"(b[1]));
}
__device__ __forceinline__ void ldsm4(uint32_t* r, uint32_t addr) {
    asm volatile("ldmatrix.sync.aligned.m8n8.x4.shared.b16 {%0,%1,%2,%3}, [%4];"
                 : "=r"(r[0]), "=r"(r[1]), "=r"(r[2]), "=r"(r[3]) : "r"(addr));
}
__device__ __forceinline__ void ldsm4t(uint32_t* r, uint32_t addr) {
    asm volatile("ldmatrix.sync.aligned.m8n8.x4.trans.shared.b16 {%0,%1,%2,%3}, [%4];"
                 : "=r"(r[0]), "=r"(r[1]), "=r"(r[2]), "=r"(r[3]) : "r"(addr));
}
__device__ __forceinline__ void cp_async16(uint32_t smem_addr, const void* gmem) {
    asm volatile("cp.async.cg.shared.global [%0], [%1], 16;"
                 :: "r"(smem_addr), "l"(gmem));
}
__device__ __forceinline__ void cp_commit() {
    asm volatile("cp.async.commit_group;" ::: "memory");
}
template <int N>
__device__ __forceinline__ void cp_wait() {
    asm volatile("cp.async.wait_group %0;" :: "n"(N) : "memory");
}
__device__ __forceinline__ uint32_t smem_u32(const void* p) {
    uint32_t a;
    asm("{ .reg .u64 t; cvta.to.shared.u64 t, %1; cvt.u32.u64 %0, t; }"
        : "=r"(a) : "l"(p));
    return a;
}
__device__ __forceinline__ uint32_t pack_h2(float lo, float hi) {
    __half2 h = __floats2half2_rn(lo, hi);
    return *reinterpret_cast<uint32_t*>(&h);
}

// ---------------------------------------------------------------------------
// fp32 -> fp16 conversion (8 elements/thread)
// ---------------------------------------------------------------------------
__global__ void __launch_bounds__(256) f2h(const float* __restrict__ s,
                                           __half* __restrict__ d)
{
    const size_t i = ((size_t)blockIdx.x * 256 + threadIdx.x) * 8;
    float4 a = *(const float4*)(s + i);
    float4 b = *(const float4*)(s + i + 4);
    __half2* dp = (__half2*)(d + i);
    dp[0] = __floats2half2_rn(a.x, a.y);
    dp[1] = __floats2half2_rn(a.z, a.w);
    dp[2] = __floats2half2_rn(b.x, b.y);
    dp[3] = __floats2half2_rn(b.z, b.w);
}

// ---------------------------------------------------------------------------
// fp16 tensor-core GEMM: C[m][n] = sum_k A[m][k] * W[n][k]   (y = x W^T)
// CTA 128x128, BK=32, 8 warps (2m x 4n), warp 64x32, m16n8k16 atoms.
// 3-stage cp.async pipeline; smem stride 40 halves (LDSM conflict-free).
// MODE 0: A = g_Xh, W by blockIdx.z, scatter fp16 to g_Q/g_K/g_V [bh,s,d]
//         (Q pre-scaled by 1/sqrt(dk))
// MODE 1: A = g_O, out = acc + bias + x (fp32 residual) -> g_Y
// ---------------------------------------------------------------------------
#define SMH 40
#define STG_B (128 * SMH * 2)          // 10240 bytes per matrix per stage
#define STAGE_B (2 * STG_B)            // 20480 bytes per stage
#define GEMM_SMEM (3 * STAGE_B)        // 61440 bytes

template <int MODE>
__global__ void __launch_bounds__(256) gemm_h(const float* __restrict__ X32,
                                              const float* __restrict__ bias)
{
    extern __shared__ char smraw[];
    const uint32_t sb = smem_u32(smraw);
    const int tid  = threadIdx.x;
    const int wid  = tid >> 5;
    const int lane = tid & 31;
    const int gid  = lane >> 2;
    const int tig  = lane & 3;
    const int wm   = wid >> 2;       // 0..1
    const int wn   = wid & 3;        // 0..3
    const int m0   = blockIdx.y * 128;
    const int n0   = blockIdx.x * 128;
    const int which = blockIdx.z;

    const __half* Ah = (MODE == 0) ? g_Xh : g_O;
    const __half* Wh = (MODE == 0)
        ? ((which == 0) ? g_Wq : (which == 1) ? g_Wk : g_Wv)
        : g_Wo;

    const int lrow = tid >> 1;             // 0..127
    const int lcol = (tid & 1) << 4;       // 0 or 16 halves

    float c[4][4][4];
#pragma unroll
    for (int mi = 0; mi < 4; mi++)
#pragma unroll
        for (int ni = 0; ni < 4; ni++)
#pragma unroll
            for (int r = 0; r < 4; r++) c[mi][ni][r] = 0.0f;

    auto load_tile = [&](int kt) {
        const int st = kt % 3;
        const int kbase = kt << 5;
        const __half* ag = Ah + (size_t)(m0 + lrow) * DM + kbase + lcol;
        const __half* wg = Wh + (size_t)(n0 + lrow) * DM + kbase + lcol;
        const uint32_t sa = sb + st * STAGE_B + (lrow * SMH + lcol) * 2;
        const uint32_t sw = sa + STG_B;
        cp_async16(sa,      ag);
        cp_async16(sa + 16, ag + 8);
        cp_async16(sw,      wg);
        cp_async16(sw + 16, wg + 8);
        cp_commit();
    };

    load_tile(0);
    load_tile(1);

    // lane-derived LDSM address components
    const int arow   = lane & 15;
    const int achunk = (lane >> 4) << 3;                       // halves
    const int brow   = (lane & 7) + ((lane >> 4) << 3);
    const int bchunk = ((lane >> 3) & 1) << 3;

    for (int kt = 0; kt < 32; ++kt) {
        if (kt == 31) cp_wait<0>(); else cp_wait<1>();
        __syncthreads();
        if (kt + 2 < 32) load_tile(kt + 2);

        const uint32_t stA = sb + (kt % 3) * STAGE_B;
        const uint32_t stB = stA + STG_B;
        const uint32_t aBase = stA + ((wm * 64 + arow) * SMH + achunk) * 2;
        const uint32_t bBase = stB + ((wn * 32 + brow) * SMH + bchunk) * 2;

#pragma unroll
        for (int ka = 0; ka < 2; ka++) {
            uint32_t af[4][4];
#pragma unroll
            for (int mi = 0; mi < 4; mi++)
                ldsm4(af[mi], aBase + (mi * 16 * SMH + ka * 16) * 2);
#pragma unroll
            for (int nip = 0; nip < 2; nip++) {
                uint32_t bf[4];
                ldsm4(bf, bBase + (nip * 16 * SMH + ka * 16) * 2);
#pragma unroll
                for (int mi = 0; mi < 4; mi++) {
                    mma_f16(c[mi][2 * nip],     af[mi], bf);
                    mma_f16(c[mi][2 * nip + 1], af[mi], bf + 2);
                }
            }
        }
        __syncthreads();
    }

    // Epilogue. c0,c1 = row gid cols 2tig,2tig+1; c2,c3 = row gid+8.
    const float qscale = (MODE == 0 && which == 0) ? 0.125f : 1.0f;
#pragma unroll
    for (int mi = 0; mi < 4; mi++) {
#pragma unroll
        for (int half = 0; half < 2; half++) {
            const int m = m0 + wm * 64 + mi * 16 + gid + half * 8;
#pragma unroll
            for (int ni = 0; ni < 4; ni++) {
                const int n = n0 + wn * 32 + ni * 8 + tig * 2;
                const float v0 = c[mi][ni][half * 2 + 0];
                const float v1 = c[mi][ni][half * 2 + 1];
                if (MODE == 0) {
                    __half* C = (which == 0) ? g_Q : (which == 1) ? g_K : g_V;
                    const int b = m >> 11;
                    const int s = m & (S_LEN - 1);
                    const int h = n >> 6;
                    const int d = n & 63;
                    *(__half2*)(C + (((size_t)(b * NH + h)) * S_LEN + s) * DK + d) =
                        __floats2half2_rn(v0 * qscale, v1 * qscale);
                } else {
                    const float* xp = X32 + (size_t)m * DM + n;
                    float2 o;
                    o.x = v0 + bias[n]     + xp[0];
                    o.y = v1 + bias[n + 1] + xp[1];
                    *(float2*)(g_Y + (size_t)m * DM + n) = o;
                }
            }
        }
    }
}

// ---------------------------------------------------------------------------
// fp16 tensor-core flash attention. 128 threads (4 warps), 64 q-rows/CTA,
// 16 q-rows/warp. K/V double-buffered cp.async. P kept in registers
// (C-fragment of scores mma == A-fragment of PV mma).
// ---------------------------------------------------------------------------
#define AST2 72                               // halves per smem row
#define ATT_ROW_B (64 * AST2 * 2)             // 9216 B per 64x64 tile
#define ATT_SMEM (5 * ATT_ROW_B)              // Q + 2K + 2V = 46080 B

__global__ void __launch_bounds__(128) flash_attn_h()
{
    extern __shared__ char smraw[];
    const uint32_t sb = smem_u32(smraw);
    const uint32_t sQ = sb;
    const uint32_t sK[2] = { sb + ATT_ROW_B,     sb + 2 * ATT_ROW_B };
    const uint32_t sV[2] = { sb + 3 * ATT_ROW_B, sb + 4 * ATT_ROW_B };

    const int tid  = threadIdx.x;
    const int wid  = tid >> 5;
    const int lane = tid & 31;
    const int gid  = lane >> 2;
    const int tig  = lane & 3;
    const int bh   = blockIdx.y;
    const int q0   = blockIdx.x * 64;

    const __half* Qg = g_Q + (size_t)bh * S_LEN * DK;
    const __half* Kg = g_K + (size_t)bh * S_LEN * DK;
    const __half* Vg = g_V + (size_t)bh * S_LEN * DK;

    const int lrow = tid >> 1;            // 0..63
    const int lcol = (tid & 1) << 5;      // 0 or 32 halves

    auto load_kv = [&](int kt) {
        const int st = kt & 1;
        const size_t gbase = (size_t)(kt * 64 + lrow) * DK + lcol;
        const uint32_t sk = sK[st] + (lrow * AST2 + lcol) * 2;
        const uint32_t sv = sV[st] + (lrow * AST2 + lcol) * 2;
#pragma unroll
        for (int j = 0; j < 4; j++) {
            cp_async16(sk + j * 16, Kg + gbase + j * 8);
            cp_async16(sv + j * 16, Vg + gbase + j * 8);
        }
        cp_commit();
    };

    load_kv(0);

    // Q tile -> smem (plain loads; done once)
#pragma unroll
    for (int j = 0; j < 4; j++) {
        *(float4*)(smraw + (lrow * AST2 + lcol + j * 8) * 2) =
            *(const float4*)(Qg + (size_t)(q0 + lrow) * DK + lcol + j * 8);
    }
    __syncthreads();

    // Persistent Q fragments: warp rows wid*16 .. +15, k = dk (4 chunks of 16)
    const int arow   = lane & 15;
    const int achunk = (lane >> 4) << 3;
    uint32_t aq[4][4];
#pragma unroll
    for (int ka = 0; ka < 4; ka++)
        ldsm4(aq[ka], sQ + ((wid * 16 + arow) * AST2 + ka * 16 + achunk) * 2);

    float co[8][4];
#pragma unroll
    for (int ni = 0; ni < 8; ni++)
#pragma unroll
        for (int r = 0; r < 4; r++) co[ni][r] = 0.0f;
    float m0 = -1e30f, m1 = -1e30f, l0 = 0.0f, l1 = 0.0f;

    // lane components for K (non-trans) and V (trans) LDSM
    const int krow   = (lane & 7) + ((lane >> 4) << 3);
    const int kchunk = ((lane >> 3) & 1) << 3;
    const int vrow   = (lane & 7) + (((lane >> 3) & 1) << 3);
    const int vchunk = (lane >> 4) << 3;

    for (int kt = 0; kt < 32; ++kt) {
        if (kt + 1 < 32) load_kv(kt + 1);
        if (kt + 1 < 32) cp_wait<1>(); else cp_wait<0>();
        __syncthreads();

        const uint32_t bK = sK[kt & 1];
        const uint32_t bV = sV[kt & 1];

        // ---- scores: 16q x 64keys ----
        float cs[8][4];
#pragma unroll
        for (int ni = 0; ni < 8; ni++)
#pragma unroll
            for (int r = 0; r < 4; r++) cs[ni][r] = 0.0f;

#pragma unroll
        for (int ka = 0; ka < 4; ka++) {
#pragma unroll
            for (int nip = 0; nip < 4; nip++) {
                uint32_t bf[4];
                ldsm4(bf, bK + ((nip * 16 + krow) * AST2 + ka * 16 + kchunk) * 2);
                mma_f16(cs[2 * nip],     aq[ka], bf);
                mma_f16(cs[2 * nip + 1], aq[ka], bf + 2);
            }
        }

        // ---- online softmax (rows gid and gid+8) ----
        float mt0 = -1e30f, mt1 = -1e30f;
#pragma unroll
        for (int ni = 0; ni < 8; ni++) {
            mt0 = fmaxf(mt0, fmaxf(cs[ni][0], cs[ni][1]));
            mt1 = fmaxf(mt1, fmaxf(cs[ni][2], cs[ni][3]));
        }
        mt0 = fmaxf(mt0, __shfl_xor_sync(0xffffffffu, mt0, 1));
        mt0 = fmaxf(mt0, __shfl_xor_sync(0xffffffffu, mt0, 2));
        mt1 = fmaxf(mt1, __shfl_xor_sync(0xffffffffu, mt1, 1));
        mt1 = fmaxf(mt1, __shfl_xor_sync(0xffffffffu, mt1, 2));

        const float m0n = fmaxf(m0, mt0);
        const float m1n = fmaxf(m1, mt1);
        const float sc0 = __expf(m0 - m0n);
        const float sc1 = __expf(m1 - m1n);
        float s0 = 0.0f, s1 = 0.0f;
#pragma unroll
        for (int ni = 0; ni < 8; ni++) {
            cs[ni][0] = __expf(cs[ni][0] - m0n);
            cs[ni][1] = __expf(cs[ni][1] - m0n);
            cs[ni][2] = __expf(cs[ni][2] - m1n);
            cs[ni][3] = __expf(cs[ni][3] - m1n);
            s0 += cs[ni][0] + cs[ni][1];
            s1 += cs[ni][2] + cs[ni][3];
        }
        s0 += __shfl_xor_sync(0xffffffffu, s0, 1);
        s0 += __shfl_xor_sync(0xffffffffu, s0, 2);
        s1 += __shfl_xor_sync(0xffffffffu, s1, 1);
        s1 += __shfl_xor_sync(0xffffffffu, s1, 2);
        l0 = l0 * sc0 + s0;
        l1 = l1 * sc1 + s1;
        m0 = m0n; m1 = m1n;
#pragma unroll
        for (int ni = 0; ni < 8; ni++) {
            co[ni][0] *= sc0; co[ni][1] *= sc0;
            co[ni][2] *= sc1; co[ni][3] *= sc1;
        }

        // ---- out += P @ V (P from registers: C-frag == A-frag layout) ----
#pragma unroll
        for (int ka = 0; ka < 4; ka++) {
            uint32_t ap[4];
            ap[0] = pack_h2(cs[2 * ka][0],     cs[2 * ka][1]);
            ap[1] = pack_h2(cs[2 * ka][2],     cs[2 * ka][3]);
            ap[2] = pack_h2(cs[2 * ka + 1][0], cs[2 * ka + 1][1]);
            ap[3] = pack_h2(cs[2 * ka + 1][2], cs[2 * ka + 1][3]);
#pragma unroll
            for (int nip = 0; nip < 4; nip++) {
                uint32_t bf[4];
                ldsm4t(bf, bV + ((ka * 16 + vrow) * AST2 + nip * 16 + vchunk) * 2);
                mma_f16(co[2 * nip],     ap, bf);
                mma_f16(co[2 * nip + 1], ap, bf + 2);
            }
        }
        __syncthreads();
    }

    // ---- epilogue: normalize, store fp16 into g_O [b*s][h*64+d] ----
    const float inv0 = 1.0f / l0;
    const float inv1 = 1.0f / l1;
    const int b = bh >> 4;
    const int h = bh & 15;
    const int r0 = q0 + wid * 16 + gid;
    __half* O0 = g_O + (size_t)(b * S_LEN + r0) * DM + h * DK;
    __half* O1 = g_O + (size_t)(b * S_LEN + r0 + 8) * DM + h * DK;
#pragma unroll
    for (int ni = 0; ni < 8; ni++) {
        *(__half2*)(O0 + ni * 8 + 2 * tig) =
            __floats2half2_rn(co[ni][0] * inv0, co[ni][1] * inv0);
        *(__half2*)(O1 + ni * 8 + 2 * tig) =
            __floats2half2_rn(co[ni][2] * inv1, co[ni][3] * inv1);
    }
}

// ---------------------------------------------------------------------------
// LayerNorm over last dim (1024). One block (256 threads) per row.
// ---------------------------------------------------------------------------
__global__ void __launch_bounds__(256) layernorm_k(const float* __restrict__ g,
                                                   const float* __restrict__ be,
                                                   float* __restrict__ out)
{
    const size_t rowbase = (size_t)blockIdx.x * DM;
    const int tid = threadIdx.x;
    const int col = tid << 2;

    float4 v = *(const float4*)(g_Y + rowbase + col);
    float sum = v.x + v.y + v.z + v.w;
    float sq  = v.x * v.x + v.y * v.y + v.z * v.z + v.w * v.w;

#pragma unroll
    for (int off = 16; off > 0; off >>= 1) {
        sum += __shfl_xor_sync(0xffffffffu, sum, off);
        sq  += __shfl_xor_sync(0xffffffffu, sq,  off);
    }
    __shared__ float s1[8], s2[8];
    const int warp = tid >> 5;
    if ((tid & 31) == 0) { s1[warp] = sum; s2[warp] = sq; }
    __syncthreads();
    float tot = 0.0f, totsq = 0.0f;
#pragma unroll
    for (int w = 0; w < 8; w++) { tot += s1[w]; totsq += s2[w]; }

    const float mean = tot * (1.0f / DM);
    const float var  = totsq * (1.0f / DM) - mean * mean;
    const float r    = rsqrtf(var + 1e-5f);

    float4 gg = *(const float4*)(g + col);
    float4 bb = *(const float4*)(be + col);
    float4 o;
    o.x = (v.x - mean) * r * gg.x + bb.x;
    o.y = (v.y - mean) * r * gg.y + bb.y;
    o.z = (v.z - mean) * r * gg.z + bb.z;
    o.w = (v.w - mean) * r * gg.w + bb.w;
    *(float4*)(out + rowbase + col) = o;
}

// ---------------------------------------------------------------------------
// Launcher
// ---------------------------------------------------------------------------
extern "C" void kernel_launch(void* const* d_in, const int* in_sizes, int n_in,
                              void* d_out, int out_size)
{
    const float* x    = (const float*)d_in[0];
    const float* w_q  = (const float*)d_in[1];
    const float* w_k  = (const float*)d_in[2];
    const float* w_v  = (const float*)d_in[3];
    const float* w_o  = (const float*)d_in[4];
    const float* b_o  = (const float*)d_in[5];
    const float* ln_g = (const float*)d_in[6];
    const float* ln_b = (const float*)d_in[7];
    float* out = (float*)d_out;

    __half *xh, *wqh, *wkh, *wvh, *woh;
    cudaGetSymbolAddress((void**)&xh,  g_Xh);
    cudaGetSymbolAddress((void**)&wqh, g_Wq);
    cudaGetSymbolAddress((void**)&wkh, g_Wk);
    cudaGetSymbolAddress((void**)&wvh, g_Wv);
    cudaGetSymbolAddress((void**)&woh, g_Wo);

    cudaFuncSetAttribute(gemm_h<0>, cudaFuncAttributeMaxDynamicSharedMemorySize, GEMM_SMEM);
    cudaFuncSetAttribute(gemm_h<1>, cudaFuncAttributeMaxDynamicSharedMemorySize, GEMM_SMEM);
    cudaFuncSetAttribute(flash_attn_h, cudaFuncAttributeMaxDynamicSharedMemorySize, ATT_SMEM);

    // fp32 -> fp16 conversions
    f2h<<<(M_TOT * DM) / (256 * 8), 256>>>(x, xh);
    f2h<<<(DM * DM) / (256 * 8), 256>>>(w_q, wqh);
    f2h<<<(DM * DM) / (256 * 8), 256>>>(w_k, wkh);
    f2h<<<(DM * DM) / (256 * 8), 256>>>(w_v, wvh);
    f2h<<<(DM * DM) / (256 * 8), 256>>>(w_o, woh);

    // Fused Q/K/V projections
    dim3 gQKV(DM / 128, M_TOT / 128, 3);   // (8, 64, 3)
    gemm_h<0><<<gQKV, 256, GEMM_SMEM>>>(x, nullptr);

    dim3 gAttn(S_LEN / 64, BATCH * NH);    // (32, 64)
    flash_attn_h<<<gAttn, 128, ATT_SMEM>>>();

    dim3 gO(DM / 128, M_TOT / 128, 1);
    gemm_h<1><<<gO, 256, GEMM_SMEM>>>(x, b_o);

    layernorm_k<<<M_TOT, 256>>>(ln_g, ln_b, out);
}

// round 7
// speedup vs baseline: 11.9750x; 1.1662x over previous
#include <cuda_runtime.h>
#include <cuda_fp16.h>
#include <cstdint>

#define BATCH   4
#define S_LEN   2048
#define DM      1024
#define NH      16
#define DK      64
#define M_TOT   (BATCH * S_LEN)   // 8192

// ---------------------------------------------------------------------------
// Scratch (device globals; no dynamic allocation allowed)
// ---------------------------------------------------------------------------
__device__ __half g_Xh[(size_t)M_TOT * DM];
__device__ __half g_Wq[(size_t)DM * DM];
__device__ __half g_Wk[(size_t)DM * DM];
__device__ __half g_Wv[(size_t)DM * DM];
__device__ __half g_Wo[(size_t)DM * DM];
__device__ __half g_Q[(size_t)BATCH * NH * S_LEN * DK];   // [bh, s, d] (pre-scaled)
__device__ __half g_K[(size_t)BATCH * NH * S_LEN * DK];
__device__ __half g_V[(size_t)BATCH * NH * S_LEN * DK];
__device__ __half g_O[(size_t)M_TOT * DM];                // attn out
__device__ float  g_Y[(size_t)M_TOT * DM];                // pre-LN residual sum

// ---------------------------------------------------------------------------
// PTX helpers (all base-target: sm_80+)
// ---------------------------------------------------------------------------
__device__ __forceinline__ void mma_f16(float* c, const uint32_t* a, const uint32_t* b) {
    asm volatile(
        "mma.sync.aligned.m16n8k16.row.col.f32.f16.f16.f32 "
        "{%0,%1,%2,%3}, {%4,%5,%6,%7}, {%8,%9}, {%0,%1,%2,%3};"
        : "+f"(c[0]), "+f"(c[1]), "+f"(c[2]), "+f"(c[3])
        : "r"(a[0]), "r"(a[1]), "r"(a[2]), "r"(a[3]), "r"(b[0]), "r"(b[1]));
}
__device__ __forceinline__ void ldsm4(uint32_t* r, uint32_t addr) {
    asm volatile("ldmatrix.sync.aligned.m8n8.x4.shared.b16 {%0,%1,%2,%3}, [%4];"
                 : "=r"(r[0]), "=r"(r[1]), "=r"(r[2]), "=r"(r[3]) : "r"(addr));
}
__device__ __forceinline__ void ldsm4t(uint32_t* r, uint32_t addr) {
    asm volatile("ldmatrix.sync.aligned.m8n8.x4.trans.shared.b16 {%0,%1,%2,%3}, [%4];"
                 : "=r"(r[0]), "=r"(r[1]), "=r"(r[2]), "=r"(r[3]) : "r"(addr));
}
__device__ __forceinline__ void cp_async16(uint32_t smem_addr, const void* gmem) {
    asm volatile("cp.async.cg.shared.global [%0], [%1], 16;"
                 :: "r"(smem_addr), "l"(gmem));
}
__device__ __forceinline__ void cp_commit() {
    asm volatile("cp.async.commit_group;" ::: "memory");
}
template <int N>
__device__ __forceinline__ void cp_wait() {
    asm volatile("cp.async.wait_group %0;" :: "n"(N) : "memory");
}
__device__ __forceinline__ uint32_t smem_u32(const void* p) {
    uint32_t a;
    asm("{ .reg .u64 t; cvta.to.shared.u64 t, %1; cvt.u32.u64 %0, t; }"
        : "=r"(a) : "l"(p));
    return a;
}
__device__ __forceinline__ uint32_t pack_h2(float lo, float hi) {
    __half2 h = __floats2half2_rn(lo, hi);
    return *reinterpret_cast<uint32_t*>(&h);
}

// ---------------------------------------------------------------------------
// fp32 -> fp16 conversions
// ---------------------------------------------------------------------------
__global__ void __launch_bounds__(256) f2h(const float* __restrict__ s,
                                           __half* __restrict__ d)
{
    const size_t i = ((size_t)blockIdx.x * 256 + threadIdx.x) * 8;
    float4 a = *(const float4*)(s + i);
    float4 b = *(const float4*)(s + i + 4);
    __half2* dp = (__half2*)(d + i);
    dp[0] = __floats2half2_rn(a.x, a.y);
    dp[1] = __floats2half2_rn(a.z, a.w);
    dp[2] = __floats2half2_rn(b.x, b.y);
    dp[3] = __floats2half2_rn(b.z, b.w);
}

__global__ void __launch_bounds__(256) w2h(const float* __restrict__ s0,
                                           const float* __restrict__ s1,
                                           const float* __restrict__ s2,
                                           const float* __restrict__ s3)
{
    const float* s = (blockIdx.y == 0) ? s0 : (blockIdx.y == 1) ? s1
                    : (blockIdx.y == 2) ? s2 : s3;
    __half* d = (blockIdx.y == 0) ? g_Wq : (blockIdx.y == 1) ? g_Wk
               : (blockIdx.y == 2) ? g_Wv : g_Wo;
    const size_t i = ((size_t)blockIdx.x * 256 + threadIdx.x) * 8;
    float4 a = *(const float4*)(s + i);
    float4 b = *(const float4*)(s + i + 4);
    __half2* dp = (__half2*)(d + i);
    dp[0] = __floats2half2_rn(a.x, a.y);
    dp[1] = __floats2half2_rn(a.z, a.w);
    dp[2] = __floats2half2_rn(b.x, b.y);
    dp[3] = __floats2half2_rn(b.z, b.w);
}

// ---------------------------------------------------------------------------
// fp16 tensor-core GEMM: C[m][n] = sum_k A[m][k] * W[n][k]   (y = x W^T)
// CTA 128x128, BK=32, 8 warps (2m x 4n), warp 64x32, m16n8k16 atoms.
// 3-stage cp.async pipeline; one barrier per k-iter.
// ---------------------------------------------------------------------------
#define SMH 40
#define STG_B (128 * SMH * 2)          // 10240 bytes per matrix per stage
#define STAGE_B (2 * STG_B)            // 20480 bytes per stage
#define GEMM_SMEM (3 * STAGE_B)        // 61440 bytes

template <int MODE>
__global__ void __launch_bounds__(256) gemm_h(const float* __restrict__ X32,
                                              const float* __restrict__ bias)
{
    extern __shared__ char smraw[];
    const uint32_t sb = smem_u32(smraw);
    const int tid  = threadIdx.x;
    const int wid  = tid >> 5;
    const int lane = tid & 31;
    const int gid  = lane >> 2;
    const int tig  = lane & 3;
    const int wm   = wid >> 2;       // 0..1
    const int wn   = wid & 3;        // 0..3
    const int m0   = blockIdx.y * 128;
    const int n0   = blockIdx.x * 128;
    const int which = blockIdx.z;

    const __half* Ah = (MODE == 0) ? g_Xh : g_O;
    const __half* Wh = (MODE == 0)
        ? ((which == 0) ? g_Wq : (which == 1) ? g_Wk : g_Wv)
        : g_Wo;

    const int lrow = tid >> 1;             // 0..127
    const int lcol = (tid & 1) << 4;       // 0 or 16 halves

    float c[4][4][4];
#pragma unroll
    for (int mi = 0; mi < 4; mi++)
#pragma unroll
        for (int ni = 0; ni < 4; ni++)
#pragma unroll
            for (int r = 0; r < 4; r++) c[mi][ni][r] = 0.0f;

    auto load_tile = [&](int kt) {
        const int st = kt % 3;
        const int kbase = kt << 5;
        const __half* ag = Ah + (size_t)(m0 + lrow) * DM + kbase + lcol;
        const __half* wg = Wh + (size_t)(n0 + lrow) * DM + kbase + lcol;
        const uint32_t sa = sb + st * STAGE_B + (lrow * SMH + lcol) * 2;
        const uint32_t sw = sa + STG_B;
        cp_async16(sa,      ag);
        cp_async16(sa + 16, ag + 8);
        cp_async16(sw,      wg);
        cp_async16(sw + 16, wg + 8);
        cp_commit();
    };

    load_tile(0);
    load_tile(1);

    // lane-derived LDSM address components
    const int arow   = lane & 15;
    const int achunk = (lane >> 4) << 3;                       // halves
    const int brow   = (lane & 7) + ((lane >> 4) << 3);
    const int bchunk = ((lane >> 3) & 1) << 3;

    for (int kt = 0; kt < 32; ++kt) {
        if (kt == 31) cp_wait<0>(); else cp_wait<1>();
        __syncthreads();
        if (kt + 2 < 32) load_tile(kt + 2);

        const uint32_t stA = sb + (kt % 3) * STAGE_B;
        const uint32_t stB = stA + STG_B;
        const uint32_t aBase = stA + ((wm * 64 + arow) * SMH + achunk) * 2;
        const uint32_t bBase = stB + ((wn * 32 + brow) * SMH + bchunk) * 2;

#pragma unroll
        for (int ka = 0; ka < 2; ka++) {
            uint32_t af[4][4];
#pragma unroll
            for (int mi = 0; mi < 4; mi++)
                ldsm4(af[mi], aBase + (mi * 16 * SMH + ka * 16) * 2);
#pragma unroll
            for (int nip = 0; nip < 2; nip++) {
                uint32_t bf[4];
                ldsm4(bf, bBase + (nip * 16 * SMH + ka * 16) * 2);
#pragma unroll
                for (int mi = 0; mi < 4; mi++) {
                    mma_f16(c[mi][2 * nip],     af[mi], bf);
                    mma_f16(c[mi][2 * nip + 1], af[mi], bf + 2);
                }
            }
        }
        // no trailing barrier: with 3 stages, the write to this stage slot
        // happens after the barrier at the top of the NEXT iteration, which
        // orders it after all reads issued in this iteration.
    }

    // Epilogue. c0,c1 = row gid cols 2tig,2tig+1; c2,c3 = row gid+8.
    const float qscale = (MODE == 0 && which == 0) ? 0.125f : 1.0f;
#pragma unroll
    for (int mi = 0; mi < 4; mi++) {
#pragma unroll
        for (int half = 0; half < 2; half++) {
            const int m = m0 + wm * 64 + mi * 16 + gid + half * 8;
#pragma unroll
            for (int ni = 0; ni < 4; ni++) {
                const int n = n0 + wn * 32 + ni * 8 + tig * 2;
                const float v0 = c[mi][ni][half * 2 + 0];
                const float v1 = c[mi][ni][half * 2 + 1];
                if (MODE == 0) {
                    __half* C = (which == 0) ? g_Q : (which == 1) ? g_K : g_V;
                    const int b = m >> 11;
                    const int s = m & (S_LEN - 1);
                    const int h = n >> 6;
                    const int d = n & 63;
                    *(__half2*)(C + (((size_t)(b * NH + h)) * S_LEN + s) * DK + d) =
                        __floats2half2_rn(v0 * qscale, v1 * qscale);
                } else {
                    const float* xp = X32 + (size_t)m * DM + n;
                    float2 o;
                    o.x = v0 + bias[n]     + xp[0];
                    o.y = v1 + bias[n + 1] + xp[1];
                    *(float2*)(g_Y + (size_t)m * DM + n) = o;
                }
            }
        }
    }
}

// ---------------------------------------------------------------------------
// fp16 tensor-core flash attention. 256 threads (8 warps), 128 q-rows/CTA,
// 16 q-rows/warp. K/V 64-key tiles double-buffered via cp.async.
// P stays in registers (score C-frag == PV A-frag layout).
// ---------------------------------------------------------------------------
#define AST2 72                               // halves per smem row
#define ATT_TILE_B (64 * AST2 * 2)            // 9216 B per 64x64 K/V tile
#define ATT_Q_B    (128 * AST2 * 2)           // 18432 B
#define ATT_SMEM   (ATT_Q_B + 4 * ATT_TILE_B) // 55296 B

__global__ void __launch_bounds__(256) flash_attn_h()
{
    extern __shared__ char smraw[];
    const uint32_t sb = smem_u32(smraw);
    const uint32_t sQ = sb;
    const uint32_t sK[2] = { sb + ATT_Q_B,                  sb + ATT_Q_B + ATT_TILE_B };
    const uint32_t sV[2] = { sb + ATT_Q_B + 2 * ATT_TILE_B, sb + ATT_Q_B + 3 * ATT_TILE_B };

    const int tid  = threadIdx.x;
    const int wid  = tid >> 5;
    const int lane = tid & 31;
    const int gid  = lane >> 2;
    const int tig  = lane & 3;
    const int bh   = blockIdx.y;
    const int q0   = blockIdx.x * 128;

    const __half* Qg = g_Q + (size_t)bh * S_LEN * DK;
    const __half* Kg = g_K + (size_t)bh * S_LEN * DK;
    const __half* Vg = g_V + (size_t)bh * S_LEN * DK;

    // K/V loads: 256 threads cover 64 rows x 64 halves per matrix.
    // Each thread owns 16 halves (32 B) -> TWO cp_async16 per matrix.
    const int kvrow = tid >> 2;            // 0..63
    const int kvcol = (tid & 3) << 4;      // 0,16,32,48 halves

    auto load_kv = [&](int kt) {
        const int st = kt & 1;
        const size_t gbase = (size_t)(kt * 64 + kvrow) * DK + kvcol;
        const uint32_t sk = sK[st] + (kvrow * AST2 + kvcol) * 2;
        const uint32_t sv = sV[st] + (kvrow * AST2 + kvcol) * 2;
        cp_async16(sk,      Kg + gbase);
        cp_async16(sk + 16, Kg + gbase + 8);
        cp_async16(sv,      Vg + gbase);
        cp_async16(sv + 16, Vg + gbase + 8);
        cp_commit();
    };

    load_kv(0);

    // Q tile -> smem (128 rows x 64 halves)
    {
        const int qrow = tid >> 1;            // 0..127
        const int qcol = (tid & 1) << 5;      // 0 or 32 halves
#pragma unroll
        for (int j = 0; j < 4; j++) {
            *(float4*)(smraw + (qrow * AST2 + qcol + j * 8) * 2) =
                *(const float4*)(Qg + (size_t)(q0 + qrow) * DK + qcol + j * 8);
        }
    }
    __syncthreads();

    // Persistent Q fragments: warp rows wid*16 .. +15
    const int arow   = lane & 15;
    const int achunk = (lane >> 4) << 3;
    uint32_t aq[4][4];
#pragma unroll
    for (int ka = 0; ka < 4; ka++)
        ldsm4(aq[ka], sQ + ((wid * 16 + arow) * AST2 + ka * 16 + achunk) * 2);

    float co[8][4];
#pragma unroll
    for (int ni = 0; ni < 8; ni++)
#pragma unroll
        for (int r = 0; r < 4; r++) co[ni][r] = 0.0f;
    float m0 = -1e30f, m1 = -1e30f, l0 = 0.0f, l1 = 0.0f;

    // lane components for K (non-trans) and V (trans) LDSM
    const int krow   = (lane & 7) + ((lane >> 4) << 3);
    const int kchunk = ((lane >> 3) & 1) << 3;
    const int vrow   = (lane & 7) + (((lane >> 3) & 1) << 3);
    const int vchunk = (lane >> 4) << 3;

    for (int kt = 0; kt < 32; ++kt) {
        if (kt + 1 < 32) load_kv(kt + 1);
        if (kt + 1 < 32) cp_wait<1>(); else cp_wait<0>();
        __syncthreads();

        const uint32_t bK = sK[kt & 1];
        const uint32_t bV = sV[kt & 1];

        // ---- scores: 16q x 64keys ----
        float cs[8][4];
#pragma unroll
        for (int ni = 0; ni < 8; ni++)
#pragma unroll
            for (int r = 0; r < 4; r++) cs[ni][r] = 0.0f;

#pragma unroll
        for (int ka = 0; ka < 4; ka++) {
#pragma unroll
            for (int nip = 0; nip < 4; nip++) {
                uint32_t bf[4];
                ldsm4(bf, bK + ((nip * 16 + krow) * AST2 + ka * 16 + kchunk) * 2);
                mma_f16(cs[2 * nip],     aq[ka], bf);
                mma_f16(cs[2 * nip + 1], aq[ka], bf + 2);
            }
        }

        // ---- online softmax (rows gid and gid+8) ----
        float mt0 = -1e30f, mt1 = -1e30f;
#pragma unroll
        for (int ni = 0; ni < 8; ni++) {
            mt0 = fmaxf(mt0, fmaxf(cs[ni][0], cs[ni][1]));
            mt1 = fmaxf(mt1, fmaxf(cs[ni][2], cs[ni][3]));
        }
        mt0 = fmaxf(mt0, __shfl_xor_sync(0xffffffffu, mt0, 1));
        mt0 = fmaxf(mt0, __shfl_xor_sync(0xffffffffu, mt0, 2));
        mt1 = fmaxf(mt1, __shfl_xor_sync(0xffffffffu, mt1, 1));
        mt1 = fmaxf(mt1, __shfl_xor_sync(0xffffffffu, mt1, 2));

        const float m0n = fmaxf(m0, mt0);
        const float m1n = fmaxf(m1, mt1);
        const float sc0 = __expf(m0 - m0n);
        const float sc1 = __expf(m1 - m1n);
        float s0 = 0.0f, s1 = 0.0f;
#pragma unroll
        for (int ni = 0; ni < 8; ni++) {
            cs[ni][0] = __expf(cs[ni][0] - m0n);
            cs[ni][1] = __expf(cs[ni][1] - m0n);
            cs[ni][2] = __expf(cs[ni][2] - m1n);
            cs[ni][3] = __expf(cs[ni][3] - m1n);
            s0 += cs[ni][0] + cs[ni][1];
            s1 += cs[ni][2] + cs[ni][3];
        }
        s0 += __shfl_xor_sync(0xffffffffu, s0, 1);
        s0 += __shfl_xor_sync(0xffffffffu, s0, 2);
        s1 += __shfl_xor_sync(0xffffffffu, s1, 1);
        s1 += __shfl_xor_sync(0xffffffffu, s1, 2);
        l0 = l0 * sc0 + s0;
        l1 = l1 * sc1 + s1;
        m0 = m0n; m1 = m1n;
#pragma unroll
        for (int ni = 0; ni < 8; ni++) {
            co[ni][0] *= sc0; co[ni][1] *= sc0;
            co[ni][2] *= sc1; co[ni][3] *= sc1;
        }

        // ---- out += P @ V ----
#pragma unroll
        for (int ka = 0; ka < 4; ka++) {
            uint32_t ap[4];
            ap[0] = pack_h2(cs[2 * ka][0],     cs[2 * ka][1]);
            ap[1] = pack_h2(cs[2 * ka][2],     cs[2 * ka][3]);
            ap[2] = pack_h2(cs[2 * ka + 1][0], cs[2 * ka + 1][1]);
            ap[3] = pack_h2(cs[2 * ka + 1][2], cs[2 * ka + 1][3]);
#pragma unroll
            for (int nip = 0; nip < 4; nip++) {
                uint32_t bf[4];
                ldsm4t(bf, bV + ((ka * 16 + vrow) * AST2 + nip * 16 + vchunk) * 2);
                mma_f16(co[2 * nip],     ap, bf);
                mma_f16(co[2 * nip + 1], ap, bf + 2);
            }
        }
        __syncthreads();
    }

    // ---- epilogue: normalize, store fp16 into g_O [b*s][h*64+d] ----
    const float inv0 = 1.0f / l0;
    const float inv1 = 1.0f / l1;
    const int b = bh >> 4;
    const int h = bh & 15;
    const int r0 = q0 + wid * 16 + gid;
    __half* O0 = g_O + (size_t)(b * S_LEN + r0) * DM + h * DK;
    __half* O1 = g_O + (size_t)(b * S_LEN + r0 + 8) * DM + h * DK;
#pragma unroll
    for (int ni = 0; ni < 8; ni++) {
        *(__half2*)(O0 + ni * 8 + 2 * tig) =
            __floats2half2_rn(co[ni][0] * inv0, co[ni][1] * inv0);
        *(__half2*)(O1 + ni * 8 + 2 * tig) =
            __floats2half2_rn(co[ni][2] * inv1, co[ni][3] * inv1);
    }
}

// ---------------------------------------------------------------------------
// LayerNorm over last dim (1024). One block (256 threads) per row.
// ---------------------------------------------------------------------------
__global__ void __launch_bounds__(256) layernorm_k(const float* __restrict__ g,
                                                   const float* __restrict__ be,
                                                   float* __restrict__ out)
{
    const size_t rowbase = (size_t)blockIdx.x * DM;
    const int tid = threadIdx.x;
    const int col = tid << 2;

    float4 v = *(const float4*)(g_Y + rowbase + col);
    float sum = v.x + v.y + v.z + v.w;
    float sq  = v.x * v.x + v.y * v.y + v.z * v.z + v.w * v.w;

#pragma unroll
    for (int off = 16; off > 0; off >>= 1) {
        sum += __shfl_xor_sync(0xffffffffu, sum, off);
        sq  += __shfl_xor_sync(0xffffffffu, sq,  off);
    }
    __shared__ float s1[8], s2[8];
    const int warp = tid >> 5;
    if ((tid & 31) == 0) { s1[warp] = sum; s2[warp] = sq; }
    __syncthreads();
    float tot = 0.0f, totsq = 0.0f;
#pragma unroll
    for (int w = 0; w < 8; w++) { tot += s1[w]; totsq += s2[w]; }

    const float mean = tot * (1.0f / DM);
    const float var  = totsq * (1.0f / DM) - mean * mean;
    const float r    = rsqrtf(var + 1e-5f);

    float4 gg = *(const float4*)(g + col);
    float4 bb = *(const float4*)(be + col);
    float4 o;
    o.x = (v.x - mean) * r * gg.x + bb.x;
    o.y = (v.y - mean) * r * gg.y + bb.y;
    o.z = (v.z - mean) * r * gg.z + bb.z;
    o.w = (v.w - mean) * r * gg.w + bb.w;
    *(float4*)(out + rowbase + col) = o;
}

// ---------------------------------------------------------------------------
// Launcher
// ---------------------------------------------------------------------------
extern "C" void kernel_launch(void* const* d_in, const int* in_sizes, int n_in,
                              void* d_out, int out_size)
{
    const float* x    = (const float*)d_in[0];
    const float* w_q  = (const float*)d_in[1];
    const float* w_k  = (const float*)d_in[2];
    const float* w_v  = (const float*)d_in[3];
    const float* w_o  = (const float*)d_in[4];
    const float* b_o  = (const float*)d_in[5];
    const float* ln_g = (const float*)d_in[6];
    const float* ln_b = (const float*)d_in[7];
    float* out = (float*)d_out;

    __half* xh;
    cudaGetSymbolAddress((void**)&xh, g_Xh);

    cudaFuncSetAttribute(gemm_h<0>, cudaFuncAttributeMaxDynamicSharedMemorySize, GEMM_SMEM);
    cudaFuncSetAttribute(gemm_h<1>, cudaFuncAttributeMaxDynamicSharedMemorySize, GEMM_SMEM);
    cudaFuncSetAttribute(flash_attn_h, cudaFuncAttributeMaxDynamicSharedMemorySize, ATT_SMEM);

    // fp32 -> fp16 conversions
    f2h<<<(M_TOT * DM) / (256 * 8), 256>>>(x, xh);
    dim3 gW((DM * DM) / (256 * 8), 4);
    w2h<<<gW, 256>>>(w_q, w_k, w_v, w_o);

    // Fused Q/K/V projections
    dim3 gQKV(DM / 128, M_TOT / 128, 3);   // (8, 64, 3)
    gemm_h<0><<<gQKV, 256, GEMM_SMEM>>>(x, nullptr);

    dim3 gAttn(S_LEN / 128, BATCH * NH);   // (16, 64)
    flash_attn_h<<<gAttn, 256, ATT_SMEM>>>();

    dim3 gO(DM / 128, M_TOT / 128, 1);
    gemm_h<1><<<gO, 256, GEMM_SMEM>>>(x, b_o);

    layernorm_k<<<M_TOT, 256>>>(ln_g, ln_b, out);
}